// round 6
// baseline (speedup 1.0000x reference)
#include <cuda_runtime.h>
#include <cuda_bf16.h>
#include <cstdint>
#include <math.h>

// Problem dims (fixed by the dataset)
#define N_TOK 8192
#define D_IN  1024
#define D_QK  128
#define D_V   1024
#define D_W1  1280   // concat rows: Wq(128) | Wk(128) | Wv(1024)
#define CAP   1024
#define LOG_THR 25.0f
#define NSM   148

// ---------------- scratch (static device globals; no allocs) ----------------
static __device__ __align__(16) __nv_bfloat16 g_xh [(size_t)N_TOK * D_IN];
static __device__ __align__(16) __nv_bfloat16 g_xl [(size_t)N_TOK * D_IN];
static __device__ __align__(16) __nv_bfloat16 g_W1h[(size_t)D_W1 * D_IN];
static __device__ __align__(16) __nv_bfloat16 g_W1l[(size_t)D_W1 * D_IN];
static __device__ __align__(16) __nv_bfloat16 g_Wlh[(size_t)D_V * D_IN];
static __device__ __align__(16) __nv_bfloat16 g_Wll[(size_t)D_V * D_IN];
static __device__ __align__(16) __nv_bfloat16 g_qkh[(size_t)N_TOK * 256];  // q:0..127 | k:128..255
static __device__ __align__(16) __nv_bfloat16 g_qkl[(size_t)N_TOK * 256];
static __device__ __align__(16) __nv_bfloat16 g_hh [(size_t)N_TOK * D_IN];
static __device__ __align__(16) __nv_bfloat16 g_hl [(size_t)N_TOK * D_IN];
static __device__ float  g_v  [(size_t)N_TOK * D_V];
static __device__ float  g_S  [(size_t)N_TOK * N_TOK];        // 256 MB
static __device__ float  g_m  [N_TOK];
static __device__ float  g_l  [N_TOK];
static __device__ int    g_cnt[N_TOK];
static __device__ float2 g_cand[(size_t)N_TOK * CAP];
static __device__ float  g_sa [(size_t)N_TOK * D_V];
static __device__ float  g_tmp[(size_t)N_TOK * D_V];

// ---------------- helpers ----------------
__device__ __forceinline__ uint32_t smem_u32(const void* p) {
    uint32_t a;
    asm("{ .reg .u64 t; cvta.to.shared.u64 t, %1; cvt.u32.u64 %0, t; }" : "=r"(a) : "l"(p));
    return a;
}
__device__ __forceinline__ void split_bf16(float v, __nv_bfloat16& h, __nv_bfloat16& l) {
    h = __float2bfloat16(v);
    l = __float2bfloat16(v - __bfloat162float(h));
}
__device__ __forceinline__ void atomicMaxFloat(float* addr, float v) {
    if (v >= 0.0f) atomicMax((int*)addr, __float_as_int(v));
    else           atomicMin((unsigned int*)addr, __float_as_uint(v));
}

#define LDSM_X4(r, addr)                                                        \
    asm volatile("ldmatrix.sync.aligned.m8n8.x4.shared.b16 {%0,%1,%2,%3}, [%4];" \
        : "=r"((r)[0]), "=r"((r)[1]), "=r"((r)[2]), "=r"((r)[3]) : "r"(addr))

#define MMA_BF16(c, a, b)                                                       \
    asm volatile("mma.sync.aligned.m16n8k16.row.col.f32.bf16.bf16.f32 "         \
        "{%0,%1,%2,%3}, {%4,%5,%6,%7}, {%8,%9}, {%0,%1,%2,%3};"                 \
        : "+f"((c)[0]), "+f"((c)[1]), "+f"((c)[2]), "+f"((c)[3])                \
        : "r"((a)[0]), "r"((a)[1]), "r"((a)[2]), "r"((a)[3]),                   \
          "r"((b)[0]), "r"((b)[1]))

#define CP_ASYNC16(dst, src) \
    asm volatile("cp.async.cg.shared.global [%0], [%1], 16;" :: "r"(dst), "l"(src))
#define CP_COMMIT()  asm volatile("cp.async.commit_group;")
#define CP_WAIT(n)   asm volatile("cp.async.wait_group %0;" :: "n"(n))

// ---------------- weight / input prep: bf16 hi-lo split ----------------
__global__ void prep_weights(const float* __restrict__ Wq, const float* __restrict__ Wk,
                             const float* __restrict__ Wv, const float* __restrict__ Wl)
{
    const int stride = gridDim.x * blockDim.x;
    int g = blockIdx.x * blockDim.x + threadIdx.x;
    for (int i = g; i < D_W1 * D_IN; i += stride) {
        int r = i >> 10, c = i & 1023;
        float v;
        if (r < 128)      v = Wq[r * D_IN + c];
        else if (r < 256) v = Wk[(r - 128) * D_IN + c];
        else              v = Wv[(r - 256) * D_IN + c];
        split_bf16(v, g_W1h[i], g_W1l[i]);
    }
    for (int i = g; i < D_V * D_IN; i += stride)
        split_bf16(Wl[i], g_Wlh[i], g_Wll[i]);
}

__global__ void split_x(const float* __restrict__ x)
{
    const int stride = gridDim.x * blockDim.x;
    int g = blockIdx.x * blockDim.x + threadIdx.x;
    for (int i = g; i < N_TOK * D_IN; i += stride)
        split_bf16(x[i], g_xh[i], g_xl[i]);
    for (int i = g; i < N_TOK; i += stride)
        g_m[i] = -1e30f;
}

// ---------------- bf16x3 tensor-core GEMM (PERSISTENT): C = alpha*A@B^T ------
// CTA tile 256x128, 8 warps (4M x 2N), warp tile 64x64, K-chunk 64.
// Larger warp tiles cut smem-read bytes/MMA from 128B to 85B (LDSM-BW bound).
#define SM_AH_OFF 0
#define SM_AL_OFF 32768
#define SM_BH_OFF 65536
#define SM_BL_OFF 81920
#define STAGE_B   98304         // 96 KB per stage
#define SMEM_BYTES (2 * STAGE_B)

__global__ __launch_bounds__(256, 1)
void gemm_mma(int mode)
{
    extern __shared__ char smem[];
    const uint32_t sb  = smem_u32(smem);
    const int tid  = threadIdx.x;
    const int wid  = tid >> 5;
    const int lane = tid & 31;

    const __nv_bfloat16 *Ah, *Al, *Bh, *Bl;
    int lda, ldb, K, ntn;
    if (mode == 0)      { Ah = g_xh;  Al = g_xl;  Bh = g_W1h;       Bl = g_W1l;       lda = 1024; ldb = 1024; K = 1024; ntn = 10; }
    else if (mode == 1) { Ah = g_qkh; Al = g_qkl; Bh = g_qkh + 128; Bl = g_qkl + 128; lda = 256;  ldb = 256;  K = 128;  ntn = 64; }
    else                { Ah = g_hh;  Al = g_hl;  Bh = g_Wlh;       Bl = g_Wll;       lda = 1024; ldb = 1024; K = 1024; ntn = 8;  }

    const int nch  = K / 64;
    const int ntot = ntn * (N_TOK / 256);

    // async fill of one stage for tile t, k-offset k0
    // A: 256 rows x 64 bf16 (hi+lo), B: 128 rows x 64 bf16 (hi+lo)
    auto load_stage = [&](int st, int t, int k0) {
        const int tm0 = (t / ntn) * 256;
        const int tn0 = (t % ntn) * 128;
        const __nv_bfloat16* bsA[2] = { Ah + (size_t)tm0 * lda, Al + (size_t)tm0 * lda };
        const __nv_bfloat16* bsB[2] = { Bh + (size_t)tn0 * ldb, Bl + (size_t)tn0 * ldb };
#pragma unroll
        for (int it = 0; it < 24; it++) {
            int idx = tid + it * 256;               // 0..6143 (16B chunks)
            const __nv_bfloat16* src;
            uint32_t dstoff;
            if (idx < 4096) {                       // A hi (0..2047) / lo (2048..4095)
                int half = idx >> 11;
                int r    = (idx >> 3) & 255;
                int g    = idx & 7;
                src = bsA[half] + (size_t)r * lda + k0 + g * 8;
                uint32_t off = (uint32_t)(r * 128 + g * 16);
                off ^= (off >> 3) & 0x70;
                dstoff = (half ? SM_AL_OFF : SM_AH_OFF) + off;
            } else {                                // B hi / lo
                int idx2 = idx - 4096;
                int half = idx2 >> 10;
                int r    = (idx2 >> 3) & 127;
                int g    = idx2 & 7;
                src = bsB[half] + (size_t)r * ldb + k0 + g * 8;
                uint32_t off = (uint32_t)(r * 128 + g * 16);
                off ^= (off >> 3) & 0x70;
                dstoff = (half ? SM_BL_OFF : SM_BH_OFF) + off;
            }
            CP_ASYNC16(sb + st * STAGE_B + dstoff, src);
        }
        CP_COMMIT();
    };

    const int wm = (wid & 3) * 64;   // warp M offset in tile (0..192)
    const int wn = (wid >> 2) * 64;  // warp N offset in tile (0 or 64)

    float acc[4][8][4];

    auto compute_stage = [&](int st) {
        const uint32_t base = sb + st * STAGE_B;
#pragma unroll
        for (int k16 = 0; k16 < 4; k16++) {
            uint32_t ah[4][4], al[4][4], bh[4][4], bl[4][4];
#pragma unroll
            for (int mi = 0; mi < 4; mi++) {
                int row = wm + mi * 16 + (lane & 15);
                int c16 = k16 * 2 + (lane >> 4);
                uint32_t off = (uint32_t)(row * 128 + c16 * 16);
                off ^= (off >> 3) & 0x70;
                LDSM_X4(ah[mi], base + SM_AH_OFF + off);
            }
#pragma unroll
            for (int nj = 0; nj < 4; nj++) {
                int row = wn + nj * 16 + (lane & 7) + ((lane >> 4) << 3);
                int c16 = k16 * 2 + ((lane >> 3) & 1);
                uint32_t off = (uint32_t)(row * 128 + c16 * 16);
                off ^= (off >> 3) & 0x70;
                LDSM_X4(bh[nj], base + SM_BH_OFF + off);
                LDSM_X4(bl[nj], base + SM_BL_OFF + off);
            }
            // term 1: ah x bh
#pragma unroll
            for (int mi = 0; mi < 4; mi++)
#pragma unroll
                for (int nj = 0; nj < 4; nj++) {
                    MMA_BF16(acc[mi][nj * 2],     ah[mi], (bh[nj] + 0));
                    MMA_BF16(acc[mi][nj * 2 + 1], ah[mi], (bh[nj] + 2));
                }
            // load al (ah still needed for term 2; allocator reuses after)
#pragma unroll
            for (int mi = 0; mi < 4; mi++) {
                int row = wm + mi * 16 + (lane & 15);
                int c16 = k16 * 2 + (lane >> 4);
                uint32_t off = (uint32_t)(row * 128 + c16 * 16);
                off ^= (off >> 3) & 0x70;
                LDSM_X4(al[mi], base + SM_AL_OFF + off);
            }
            // term 2: ah x bl
#pragma unroll
            for (int mi = 0; mi < 4; mi++)
#pragma unroll
                for (int nj = 0; nj < 4; nj++) {
                    MMA_BF16(acc[mi][nj * 2],     ah[mi], (bl[nj] + 0));
                    MMA_BF16(acc[mi][nj * 2 + 1], ah[mi], (bl[nj] + 2));
                }
            // term 3: al x bh
#pragma unroll
            for (int mi = 0; mi < 4; mi++)
#pragma unroll
                for (int nj = 0; nj < 4; nj++) {
                    MMA_BF16(acc[mi][nj * 2],     al[mi], (bh[nj] + 0));
                    MMA_BF16(acc[mi][nj * 2 + 1], al[mi], (bh[nj] + 2));
                }
        }
    };

    const int qr = lane >> 2;
    const int qc = (lane & 3) * 2;

    // epilogue for tile t
    auto epilogue = [&](int t) {
        const int m0 = (t / ntn) * 256;
        const int n0 = (t % ntn) * 128;
        if (mode == 1) {
            const float alpha = 11.313708498984760f; // sqrt(128)
#pragma unroll
            for (int mi = 0; mi < 4; mi++) {
                float rmax0 = -1e30f, rmax1 = -1e30f;
                const int r0 = m0 + wm + mi * 16 + qr;
#pragma unroll
                for (int ni = 0; ni < 8; ni++) {
                    const int col = n0 + wn + ni * 8 + qc;
                    float c0 = alpha * acc[mi][ni][0], c1 = alpha * acc[mi][ni][1];
                    float c2 = alpha * acc[mi][ni][2], c3 = alpha * acc[mi][ni][3];
                    rmax0 = fmaxf(rmax0, fmaxf(c0, c1));
                    rmax1 = fmaxf(rmax1, fmaxf(c2, c3));
                    *(float2*)(g_S + (size_t)r0 * N_TOK + col)       = make_float2(c0, c1);
                    *(float2*)(g_S + (size_t)(r0 + 8) * N_TOK + col) = make_float2(c2, c3);
                }
#pragma unroll
                for (int s = 1; s < 4; s <<= 1) {
                    rmax0 = fmaxf(rmax0, __shfl_xor_sync(0xFFFFFFFF, rmax0, s));
                    rmax1 = fmaxf(rmax1, __shfl_xor_sync(0xFFFFFFFF, rmax1, s));
                }
                if ((lane & 3) == 0) {
                    atomicMaxFloat(&g_m[r0],     rmax0);
                    atomicMaxFloat(&g_m[r0 + 8], rmax1);
                }
            }
        } else if (mode == 0) {
#pragma unroll
            for (int mi = 0; mi < 4; mi++) {
                const int r0 = m0 + wm + mi * 16 + qr;
#pragma unroll
                for (int ni = 0; ni < 8; ni++) {
                    const int col = n0 + wn + ni * 8 + qc;
                    if (col < 256) {
                        __nv_bfloat16 h0, l0, h1, l1;
#pragma unroll
                        for (int half = 0; half < 2; half++) {
                            const int rr = r0 + half * 8;
                            split_bf16(acc[mi][ni][half * 2 + 0], h0, l0);
                            split_bf16(acc[mi][ni][half * 2 + 1], h1, l1);
                            *(__nv_bfloat162*)(g_qkh + (size_t)rr * 256 + col) =
                                __nv_bfloat162(h0, h1);
                            *(__nv_bfloat162*)(g_qkl + (size_t)rr * 256 + col) =
                                __nv_bfloat162(l0, l1);
                        }
                    } else {
                        const int vc = col - 256;
                        *(float2*)(g_v + (size_t)r0 * D_V + vc) =
                            make_float2(acc[mi][ni][0], acc[mi][ni][1]);
                        *(float2*)(g_v + (size_t)(r0 + 8) * D_V + vc) =
                            make_float2(acc[mi][ni][2], acc[mi][ni][3]);
                    }
                }
            }
        } else {
#pragma unroll
            for (int mi = 0; mi < 4; mi++) {
                const int r0 = m0 + wm + mi * 16 + qr;
#pragma unroll
                for (int ni = 0; ni < 8; ni++) {
                    const int col = n0 + wn + ni * 8 + qc;
                    *(float2*)(g_tmp + (size_t)r0 * D_V + col) =
                        make_float2(acc[mi][ni][0], acc[mi][ni][1]);
                    *(float2*)(g_tmp + (size_t)(r0 + 8) * D_V + col) =
                        make_float2(acc[mi][ni][2], acc[mi][ni][3]);
                }
            }
        }
    };

    // ---------------- persistent tile loop with continuous pipeline ----------
    int t0 = blockIdx.x;
    if (t0 >= ntot) return;
    load_stage(0, t0, 0);
    int buf = 0;

    for (int t = t0; t < ntot; t += gridDim.x) {
        const int tnext = t + gridDim.x;
#pragma unroll
        for (int i = 0; i < 4; i++)
#pragma unroll
            for (int j = 0; j < 8; j++)
#pragma unroll
                for (int k = 0; k < 4; k++) acc[i][j][k] = 0.0f;

        for (int ch = 0; ch < nch; ch++) {
            const bool more_chunk = (ch + 1 < nch);
            if (more_chunk)            load_stage(buf ^ 1, t, (ch + 1) * 64);
            else if (tnext < ntot)     load_stage(buf ^ 1, tnext, 0);
            if (more_chunk || tnext < ntot) { CP_WAIT(1); }
            else                            { CP_WAIT(0); }
            __syncthreads();
            compute_stage(buf);
            buf ^= 1;
            __syncthreads();
        }
        epilogue(t);
    }
}

// ---------------- softmax: single pass (max precomputed in scores epilogue) ---
__global__ __launch_bounds__(256)
void softmax_stats()
{
    const int r   = blockIdx.x;
    const int tid = threadIdx.x;
    const float* Srow = g_S + (size_t)r * N_TOK;
    const float m = g_m[r];

    __shared__ float red[256];
    __shared__ int   sc[256];
    __shared__ int   s_over;
    if (tid == 0) s_over = 0;
    __syncthreads();

    const float thr = m - LOG_THR;
    float lsum = 0.0f;
    int   lj[8]; float lw[8];
    int   lc = 0; int over = 0;
    for (int j = tid; j < N_TOK; j += 256) {
        float s = Srow[j];
        float w = __expf(s - m);
        lsum += w;
        if (s > thr) {
            if (lc < 8) { lj[lc] = j; lw[lc] = w; }
            else over = 1;
            lc++;
        }
    }
    if (over) atomicOr(&s_over, 1);
    red[tid] = lsum;
    __syncthreads();
    for (int s = 128; s > 0; s >>= 1) {
        if (tid < s) red[tid] += red[tid + s];
        __syncthreads();
    }
    const float l = red[0];

    sc[tid] = lc;
    __syncthreads();
    for (int off = 1; off < 256; off <<= 1) {
        int tsc = (tid >= off) ? sc[tid - off] : 0;
        __syncthreads();
        sc[tid] += tsc;
        __syncthreads();
    }
    const int total = sc[255];
    const int myoff = sc[tid] - lc;
    const int dense = (total > CAP) || (s_over != 0);

    if (!dense) {
        const int n = (lc < 8) ? lc : 8;
        for (int i = 0; i < n; i++)
            g_cand[(size_t)r * CAP + myoff + i] =
                make_float2(__int_as_float(lj[i]), lw[i]);
    }
    if (tid == 0) {
        g_l[r]   = l;
        g_cnt[r] = dense ? (CAP + 1) : total;
    }
}

// ---------------- sparse attn@v ----------------
__global__ __launch_bounds__(64)
void attn_av()
{
    const int r   = blockIdx.x;
    const int tid = threadIdx.x;
    const int cnt = g_cnt[r];
    const float invl = 1.0f / g_l[r];
    const int d = tid * 16;

    float4 a0 = make_float4(0, 0, 0, 0), a1 = a0, a2 = a0, a3 = a0;

    if (cnt <= CAP) {
        const float2* cl = g_cand + (size_t)r * CAP;
        for (int i = 0; i < cnt; i++) {
            float2 c = cl[i];
            int   j = __float_as_int(c.x);
            float w = c.y * invl;
            const float* vr = g_v + (size_t)j * D_V + d;
            float4 v0 = *(const float4*)(vr);
            float4 v1 = *(const float4*)(vr + 4);
            float4 v2 = *(const float4*)(vr + 8);
            float4 v3 = *(const float4*)(vr + 12);
            a0.x += w * v0.x; a0.y += w * v0.y; a0.z += w * v0.z; a0.w += w * v0.w;
            a1.x += w * v1.x; a1.y += w * v1.y; a1.z += w * v1.z; a1.w += w * v1.w;
            a2.x += w * v2.x; a2.y += w * v2.y; a2.z += w * v2.z; a2.w += w * v2.w;
            a3.x += w * v3.x; a3.y += w * v3.y; a3.z += w * v3.z; a3.w += w * v3.w;
        }
    } else {
        const float m = g_m[r];
        const float* Srow = g_S + (size_t)r * N_TOK;
        for (int j = 0; j < N_TOK; j++) {
            float w = __expf(Srow[j] - m) * invl;
            if (w > 1e-12f) {
                const float* vr = g_v + (size_t)j * D_V + d;
                float4 v0 = *(const float4*)(vr);
                float4 v1 = *(const float4*)(vr + 4);
                float4 v2 = *(const float4*)(vr + 8);
                float4 v3 = *(const float4*)(vr + 12);
                a0.x += w * v0.x; a0.y += w * v0.y; a0.z += w * v0.z; a0.w += w * v0.w;
                a1.x += w * v1.x; a1.y += w * v1.y; a1.z += w * v1.z; a1.w += w * v1.w;
                a2.x += w * v2.x; a2.y += w * v2.y; a2.z += w * v2.z; a2.w += w * v2.w;
                a3.x += w * v3.x; a3.y += w * v3.y; a3.z += w * v3.z; a3.w += w * v3.w;
            }
        }
    }

    float* out = g_sa + (size_t)r * D_V + d;
    *(float4*)(out)      = a0;
    *(float4*)(out + 4)  = a1;
    *(float4*)(out + 8)  = a2;
    *(float4*)(out + 12) = a3;
}

// ---------------- fused residual + LayerNorm ----------------
__global__ __launch_bounds__(256)
void ln_fuse(int mode, const float* __restrict__ ext_a, float* __restrict__ ext_out)
{
    const int r   = blockIdx.x;
    const int tid = threadIdx.x;
    const float* a; const float* b;
    if (mode == 0) { a = ext_a; b = g_sa; }
    else           { a = g_sa;  b = g_tmp; }

    const float4 av = *(const float4*)(a + (size_t)r * D_V + tid * 4);
    const float4 bv = *(const float4*)(b + (size_t)r * D_V + tid * 4);
    float4 y = make_float4(av.x + bv.x, av.y + bv.y, av.z + bv.z, av.w + bv.w);

    float s  = y.x + y.y + y.z + y.w;
    float sq = y.x * y.x + y.y * y.y + y.z * y.z + y.w * y.w;

    __shared__ float2 red2[256];
    red2[tid] = make_float2(s, sq);
    __syncthreads();
    for (int st = 128; st > 0; st >>= 1) {
        if (tid < st) {
            red2[tid].x += red2[tid + st].x;
            red2[tid].y += red2[tid + st].y;
        }
        __syncthreads();
    }
    const float mean = red2[0].x * (1.0f / (float)D_V);
    const float var  = red2[0].y * (1.0f / (float)D_V) - mean * mean;
    const float rstd = rsqrtf(var + 1e-5f);

    float o0 = (y.x - mean) * rstd, o1 = (y.y - mean) * rstd;
    float o2 = (y.z - mean) * rstd, o3 = (y.w - mean) * rstd;

    if (mode == 0) {
        size_t base = (size_t)r * D_V + tid * 4;
        split_bf16(o0, g_hh[base + 0], g_hl[base + 0]);
        split_bf16(o1, g_hh[base + 1], g_hl[base + 1]);
        split_bf16(o2, g_hh[base + 2], g_hl[base + 2]);
        split_bf16(o3, g_hh[base + 3], g_hl[base + 3]);
    } else {
        *(float4*)(ext_out + (size_t)r * D_V + tid * 4) = make_float4(o0, o1, o2, o3);
    }
}

// ---------------- launch sequence ----------------
extern "C" void kernel_launch(void* const* d_in, const int* in_sizes, int n_in,
                              void* d_out, int out_size)
{
    const float* x  = (const float*)d_in[0];
    const float* Wq = (const float*)d_in[1];
    const float* Wk = (const float*)d_in[2];
    const float* Wv = (const float*)d_in[3];
    const float* Wl = (const float*)d_in[4];
    float* out = (float*)d_out;

    cudaFuncSetAttribute(gemm_mma, cudaFuncAttributeMaxDynamicSharedMemorySize, SMEM_BYTES);

    prep_weights<<<256, 256>>>(Wq, Wk, Wv, Wl);
    split_x<<<512, 256>>>(x);

    // qkv = x @ W1^T  (M=8192, N=1280, K=1024) -> qk bf16 split + v fp32
    gemm_mma<<<NSM, 256, SMEM_BYTES>>>(0);

    // S = sqrt(128) * q @ k^T  (M=N=8192, K=128) + row-max atomics
    gemm_mma<<<NSM, 256, SMEM_BYTES>>>(1);

    softmax_stats<<<N_TOK, 256>>>();
    attn_av<<<N_TOK, 64>>>();
    ln_fuse<<<N_TOK, 256>>>(0, x, nullptr);

    // tmp = h @ Wl^T  (M=8192, N=1024, K=1024)
    gemm_mma<<<NSM, 256, SMEM_BYTES>>>(2);

    ln_fuse<<<N_TOK, 256>>>(1, nullptr, out);
}

// round 8
// speedup vs baseline: 1.0143x; 1.0143x over previous
#include <cuda_runtime.h>
#include <cuda_bf16.h>
#include <cstdint>
#include <math.h>

// Problem dims (fixed by the dataset)
#define N_TOK 8192
#define D_IN  1024
#define D_QK  128
#define D_V   1024
#define D_W1  1280   // concat rows: Wq(128) | Wk(128) | Wv(1024)
#define CAP   1024
#define LOG_THR 25.0f
#define NSM   148

// ---------------- scratch (static device globals; no allocs) ----------------
static __device__ __align__(16) __nv_bfloat16 g_xh [(size_t)N_TOK * D_IN];
static __device__ __align__(16) __nv_bfloat16 g_xl [(size_t)N_TOK * D_IN];
static __device__ __align__(16) __nv_bfloat16 g_W1h[(size_t)D_W1 * D_IN];
static __device__ __align__(16) __nv_bfloat16 g_W1l[(size_t)D_W1 * D_IN];
static __device__ __align__(16) __nv_bfloat16 g_Wlh[(size_t)D_V * D_IN];
static __device__ __align__(16) __nv_bfloat16 g_Wll[(size_t)D_V * D_IN];
static __device__ __align__(16) __nv_bfloat16 g_qkh[(size_t)N_TOK * 256];  // q:0..127 | k:128..255
static __device__ __align__(16) __nv_bfloat16 g_qkl[(size_t)N_TOK * 256];
static __device__ __align__(16) __nv_bfloat16 g_hh [(size_t)N_TOK * D_IN];
static __device__ __align__(16) __nv_bfloat16 g_hl [(size_t)N_TOK * D_IN];
static __device__ float  g_v  [(size_t)N_TOK * D_V];
static __device__ float  g_S  [(size_t)N_TOK * N_TOK];        // 256 MB
static __device__ float  g_m  [N_TOK];
static __device__ float  g_l  [N_TOK];
static __device__ int    g_cnt[N_TOK];
static __device__ float2 g_cand[(size_t)N_TOK * CAP];
static __device__ float  g_sa [(size_t)N_TOK * D_V];
static __device__ float  g_tmp[(size_t)N_TOK * D_V];

// ---------------- helpers ----------------
__device__ __forceinline__ uint32_t smem_u32(const void* p) {
    uint32_t a;
    asm("{ .reg .u64 t; cvta.to.shared.u64 t, %1; cvt.u32.u64 %0, t; }" : "=r"(a) : "l"(p));
    return a;
}
__device__ __forceinline__ void split_bf16(float v, __nv_bfloat16& h, __nv_bfloat16& l) {
    h = __float2bfloat16(v);
    l = __float2bfloat16(v - __bfloat162float(h));
}
__device__ __forceinline__ void atomicMaxFloat(float* addr, float v) {
    if (v >= 0.0f) atomicMax((int*)addr, __float_as_int(v));
    else           atomicMin((unsigned int*)addr, __float_as_uint(v));
}

#define LDSM_X4(r, addr)                                                        \
    asm volatile("ldmatrix.sync.aligned.m8n8.x4.shared.b16 {%0,%1,%2,%3}, [%4];" \
        : "=r"((r)[0]), "=r"((r)[1]), "=r"((r)[2]), "=r"((r)[3]) : "r"(addr))

#define MMA_BF16(c, a, b)                                                       \
    asm volatile("mma.sync.aligned.m16n8k16.row.col.f32.bf16.bf16.f32 "         \
        "{%0,%1,%2,%3}, {%4,%5,%6,%7}, {%8,%9}, {%0,%1,%2,%3};"                 \
        : "+f"((c)[0]), "+f"((c)[1]), "+f"((c)[2]), "+f"((c)[3])                \
        : "r"((a)[0]), "r"((a)[1]), "r"((a)[2]), "r"((a)[3]),                   \
          "r"((b)[0]), "r"((b)[1]))

#define CP_ASYNC16(dst, src) \
    asm volatile("cp.async.cg.shared.global [%0], [%1], 16;" :: "r"(dst), "l"(src))
#define CP_COMMIT()  asm volatile("cp.async.commit_group;")
#define CP_WAIT(n)   asm volatile("cp.async.wait_group %0;" :: "n"(n))

// ---------------- weight / input prep: bf16 hi-lo split ----------------
__global__ void prep_weights(const float* __restrict__ Wq, const float* __restrict__ Wk,
                             const float* __restrict__ Wv, const float* __restrict__ Wl)
{
    const int stride = gridDim.x * blockDim.x;
    int g = blockIdx.x * blockDim.x + threadIdx.x;
    for (int i = g; i < D_W1 * D_IN; i += stride) {
        int r = i >> 10, c = i & 1023;
        float v;
        if (r < 128)      v = Wq[r * D_IN + c];
        else if (r < 256) v = Wk[(r - 128) * D_IN + c];
        else              v = Wv[(r - 256) * D_IN + c];
        split_bf16(v, g_W1h[i], g_W1l[i]);
    }
    for (int i = g; i < D_V * D_IN; i += stride)
        split_bf16(Wl[i], g_Wlh[i], g_Wll[i]);
}

__global__ void split_x(const float* __restrict__ x)
{
    const int stride = gridDim.x * blockDim.x;
    int g = blockIdx.x * blockDim.x + threadIdx.x;
    for (int i = g; i < N_TOK * D_IN; i += stride)
        split_bf16(x[i], g_xh[i], g_xl[i]);
    for (int i = g; i < N_TOK; i += stride)
        g_m[i] = -1e30f;
}

// ---------------- bf16x3 tensor-core GEMM (PERSISTENT): C = alpha*A@B^T ------
// CTA tile 128x128, K-chunk 64, 8 warps (warp tile 32x64), 2-stage cp.async,
// and REGISTER double-buffered fragments: LDSM for k16+1 issue between the MMA
// terms of k16 so ldmatrix latency is covered by independent tensor work.
#define TILE_B   16384          // one 128x64 bf16 tile (swizzled)
#define STAGE_B  (4 * TILE_B)   // Ah, Al, Bh, Bl
#define SMEM_BYTES (2 * STAGE_B)

__global__ __launch_bounds__(256, 1)
void gemm_mma(int mode)
{
    extern __shared__ char smem[];
    const uint32_t sb  = smem_u32(smem);
    const int tid  = threadIdx.x;
    const int wid  = tid >> 5;
    const int lane = tid & 31;

    const __nv_bfloat16 *Ah, *Al, *Bh, *Bl;
    int lda, ldb, K, ntn;
    if (mode == 0)      { Ah = g_xh;  Al = g_xl;  Bh = g_W1h;       Bl = g_W1l;       lda = 1024; ldb = 1024; K = 1024; ntn = 10; }
    else if (mode == 1) { Ah = g_qkh; Al = g_qkl; Bh = g_qkh + 128; Bl = g_qkl + 128; lda = 256;  ldb = 256;  K = 128;  ntn = 64; }
    else                { Ah = g_hh;  Al = g_hl;  Bh = g_Wlh;       Bl = g_Wll;       lda = 1024; ldb = 1024; K = 1024; ntn = 8;  }

    const int nch  = K / 64;
    const int ntot = ntn * (N_TOK / 128);

    // async fill of one stage for tile t, k-offset k0
    auto load_stage = [&](int st, int t, int k0) {
        const int tm0 = (t / ntn) * 128;
        const int tn0 = (t % ntn) * 128;
        const __nv_bfloat16* bs[4] = {
            Ah + (size_t)tm0 * lda, Al + (size_t)tm0 * lda,
            Bh + (size_t)tn0 * ldb, Bl + (size_t)tn0 * ldb };
        const int ldt[4] = { lda, lda, ldb, ldb };
#pragma unroll
        for (int it = 0; it < 16; it++) {
            int idx  = tid + it * 256;
            int tile = idx >> 10;
            int r    = (idx >> 3) & 127;
            int g    = idx & 7;
            const __nv_bfloat16* src = bs[tile] + (size_t)r * ldt[tile] + k0 + g * 8;
            uint32_t off = (uint32_t)(r * 128 + g * 16);
            off ^= (off >> 3) & 0x70;
            CP_ASYNC16(sb + st * STAGE_B + tile * TILE_B + off, src);
        }
        CP_COMMIT();
    };

    const int wm = (wid & 3) * 32;   // warp M offset in tile
    const int wn = (wid >> 2) * 64;  // warp N offset in tile

    float acc[2][8][4];

    // fragment loader for one k16 step into the given buffers
    auto load_frags = [&](uint32_t base, int k16,
                          uint32_t (*ah)[4], uint32_t (*al)[4],
                          uint32_t (*bh)[4], uint32_t (*bl)[4]) {
#pragma unroll
        for (int mi = 0; mi < 2; mi++) {
            int row = wm + mi * 16 + (lane & 15);
            int c16 = k16 * 2 + (lane >> 4);
            uint32_t off = (uint32_t)(row * 128 + c16 * 16);
            off ^= (off >> 3) & 0x70;
            LDSM_X4(ah[mi], base + 0 * TILE_B + off);
            LDSM_X4(al[mi], base + 1 * TILE_B + off);
        }
#pragma unroll
        for (int nj = 0; nj < 4; nj++) {
            int row = wn + nj * 16 + (lane & 7) + ((lane >> 4) << 3);
            int c16 = k16 * 2 + ((lane >> 3) & 1);
            uint32_t off = (uint32_t)(row * 128 + c16 * 16);
            off ^= (off >> 3) & 0x70;
            LDSM_X4(bh[nj], base + 2 * TILE_B + off);
            LDSM_X4(bl[nj], base + 3 * TILE_B + off);
        }
    };

    auto compute_stage = [&](int st) {
        const uint32_t base = sb + st * STAGE_B;
        uint32_t ah[2][2][4], al[2][2][4], bh[2][4][4], bl[2][4][4];
        load_frags(base, 0, ah[0], al[0], bh[0], bl[0]);
#pragma unroll
        for (int k16 = 0; k16 < 4; k16++) {
            const int cur = k16 & 1;
            // term 1: ah x bh
#pragma unroll
            for (int mi = 0; mi < 2; mi++)
#pragma unroll
                for (int nj = 0; nj < 4; nj++) {
                    MMA_BF16(acc[mi][nj * 2],     ah[cur][mi], (bh[cur][nj] + 0));
                    MMA_BF16(acc[mi][nj * 2 + 1], ah[cur][mi], (bh[cur][nj] + 2));
                }
            // prefetch next k16 fragments into the other buffer; the LDSM
            // latency is covered by terms 2+3 below (32 independent MMAs)
            if (k16 < 3)
                load_frags(base, k16 + 1, ah[cur ^ 1], al[cur ^ 1],
                           bh[cur ^ 1], bl[cur ^ 1]);
            // term 2: ah x bl
#pragma unroll
            for (int mi = 0; mi < 2; mi++)
#pragma unroll
                for (int nj = 0; nj < 4; nj++) {
                    MMA_BF16(acc[mi][nj * 2],     ah[cur][mi], (bl[cur][nj] + 0));
                    MMA_BF16(acc[mi][nj * 2 + 1], ah[cur][mi], (bl[cur][nj] + 2));
                }
            // term 3: al x bh
#pragma unroll
            for (int mi = 0; mi < 2; mi++)
#pragma unroll
                for (int nj = 0; nj < 4; nj++) {
                    MMA_BF16(acc[mi][nj * 2],     al[cur][mi], (bh[cur][nj] + 0));
                    MMA_BF16(acc[mi][nj * 2 + 1], al[cur][mi], (bh[cur][nj] + 2));
                }
        }
    };

    const int qr = lane >> 2;
    const int qc = (lane & 3) * 2;

    // epilogue for tile t
    auto epilogue = [&](int t) {
        const int m0 = (t / ntn) * 128;
        const int n0 = (t % ntn) * 128;
        if (mode == 1) {
            const float alpha = 11.313708498984760f; // sqrt(128)
            float rmax0[2] = { -1e30f, -1e30f };
            float rmax1[2] = { -1e30f, -1e30f };
#pragma unroll
            for (int mi = 0; mi < 2; mi++) {
                const int r0 = m0 + wm + mi * 16 + qr;
#pragma unroll
                for (int ni = 0; ni < 8; ni++) {
                    const int col = n0 + wn + ni * 8 + qc;
                    float c0 = alpha * acc[mi][ni][0], c1 = alpha * acc[mi][ni][1];
                    float c2 = alpha * acc[mi][ni][2], c3 = alpha * acc[mi][ni][3];
                    rmax0[mi] = fmaxf(rmax0[mi], fmaxf(c0, c1));
                    rmax1[mi] = fmaxf(rmax1[mi], fmaxf(c2, c3));
                    *(float2*)(g_S + (size_t)r0 * N_TOK + col)       = make_float2(c0, c1);
                    *(float2*)(g_S + (size_t)(r0 + 8) * N_TOK + col) = make_float2(c2, c3);
                }
            }
#pragma unroll
            for (int mi = 0; mi < 2; mi++) {
#pragma unroll
                for (int s = 1; s < 4; s <<= 1) {
                    rmax0[mi] = fmaxf(rmax0[mi], __shfl_xor_sync(0xFFFFFFFF, rmax0[mi], s));
                    rmax1[mi] = fmaxf(rmax1[mi], __shfl_xor_sync(0xFFFFFFFF, rmax1[mi], s));
                }
                if ((lane & 3) == 0) {
                    const int r0 = m0 + wm + mi * 16 + qr;
                    atomicMaxFloat(&g_m[r0],     rmax0[mi]);
                    atomicMaxFloat(&g_m[r0 + 8], rmax1[mi]);
                }
            }
        } else if (mode == 0) {
#pragma unroll
            for (int mi = 0; mi < 2; mi++) {
                const int r0 = m0 + wm + mi * 16 + qr;
#pragma unroll
                for (int ni = 0; ni < 8; ni++) {
                    const int col = n0 + wn + ni * 8 + qc;
                    if (col < 256) {
                        __nv_bfloat16 h0, l0, h1, l1;
#pragma unroll
                        for (int half = 0; half < 2; half++) {
                            const int rr = r0 + half * 8;
                            split_bf16(acc[mi][ni][half * 2 + 0], h0, l0);
                            split_bf16(acc[mi][ni][half * 2 + 1], h1, l1);
                            *(__nv_bfloat162*)(g_qkh + (size_t)rr * 256 + col) =
                                __nv_bfloat162(h0, h1);
                            *(__nv_bfloat162*)(g_qkl + (size_t)rr * 256 + col) =
                                __nv_bfloat162(l0, l1);
                        }
                    } else {
                        const int vc = col - 256;
                        *(float2*)(g_v + (size_t)r0 * D_V + vc) =
                            make_float2(acc[mi][ni][0], acc[mi][ni][1]);
                        *(float2*)(g_v + (size_t)(r0 + 8) * D_V + vc) =
                            make_float2(acc[mi][ni][2], acc[mi][ni][3]);
                    }
                }
            }
        } else {
#pragma unroll
            for (int mi = 0; mi < 2; mi++) {
                const int r0 = m0 + wm + mi * 16 + qr;
#pragma unroll
                for (int ni = 0; ni < 8; ni++) {
                    const int col = n0 + wn + ni * 8 + qc;
                    *(float2*)(g_tmp + (size_t)r0 * D_V + col) =
                        make_float2(acc[mi][ni][0], acc[mi][ni][1]);
                    *(float2*)(g_tmp + (size_t)(r0 + 8) * D_V + col) =
                        make_float2(acc[mi][ni][2], acc[mi][ni][3]);
                }
            }
        }
    };

    // ---------------- persistent tile loop with continuous pipeline ----------
    int t0 = blockIdx.x;
    if (t0 >= ntot) return;
    load_stage(0, t0, 0);
    int buf = 0;

    for (int t = t0; t < ntot; t += gridDim.x) {
        const int tnext = t + gridDim.x;
#pragma unroll
        for (int i = 0; i < 2; i++)
#pragma unroll
            for (int j = 0; j < 8; j++)
#pragma unroll
                for (int k = 0; k < 4; k++) acc[i][j][k] = 0.0f;

        for (int ch = 0; ch < nch; ch++) {
            const bool more_chunk = (ch + 1 < nch);
            if (more_chunk)            load_stage(buf ^ 1, t, (ch + 1) * 64);
            else if (tnext < ntot)     load_stage(buf ^ 1, tnext, 0);
            if (more_chunk || tnext < ntot) { CP_WAIT(1); }
            else                            { CP_WAIT(0); }
            __syncthreads();
            compute_stage(buf);
            buf ^= 1;
            __syncthreads();
        }
        epilogue(t);
    }
}

// ---------------- softmax: single pass (max precomputed in scores epilogue) ---
__global__ __launch_bounds__(256)
void softmax_stats()
{
    const int r   = blockIdx.x;
    const int tid = threadIdx.x;
    const float* Srow = g_S + (size_t)r * N_TOK;
    const float m = g_m[r];

    __shared__ float red[256];
    __shared__ int   sc[256];
    __shared__ int   s_over;
    if (tid == 0) s_over = 0;
    __syncthreads();

    const float thr = m - LOG_THR;
    float lsum = 0.0f;
    int   lj[8]; float lw[8];
    int   lc = 0; int over = 0;
    for (int j = tid; j < N_TOK; j += 256) {
        float s = Srow[j];
        float w = __expf(s - m);
        lsum += w;
        if (s > thr) {
            if (lc < 8) { lj[lc] = j; lw[lc] = w; }
            else over = 1;
            lc++;
        }
    }
    if (over) atomicOr(&s_over, 1);
    red[tid] = lsum;
    __syncthreads();
    for (int s = 128; s > 0; s >>= 1) {
        if (tid < s) red[tid] += red[tid + s];
        __syncthreads();
    }
    const float l = red[0];

    sc[tid] = lc;
    __syncthreads();
    for (int off = 1; off < 256; off <<= 1) {
        int tsc = (tid >= off) ? sc[tid - off] : 0;
        __syncthreads();
        sc[tid] += tsc;
        __syncthreads();
    }
    const int total = sc[255];
    const int myoff = sc[tid] - lc;
    const int dense = (total > CAP) || (s_over != 0);

    if (!dense) {
        const int n = (lc < 8) ? lc : 8;
        for (int i = 0; i < n; i++)
            g_cand[(size_t)r * CAP + myoff + i] =
                make_float2(__int_as_float(lj[i]), lw[i]);
    }
    if (tid == 0) {
        g_l[r]   = l;
        g_cnt[r] = dense ? (CAP + 1) : total;
    }
}

// ---------------- sparse attn@v ----------------
__global__ __launch_bounds__(64)
void attn_av()
{
    const int r   = blockIdx.x;
    const int tid = threadIdx.x;
    const int cnt = g_cnt[r];
    const float invl = 1.0f / g_l[r];
    const int d = tid * 16;

    float4 a0 = make_float4(0, 0, 0, 0), a1 = a0, a2 = a0, a3 = a0;

    if (cnt <= CAP) {
        const float2* cl = g_cand + (size_t)r * CAP;
        for (int i = 0; i < cnt; i++) {
            float2 c = cl[i];
            int   j = __float_as_int(c.x);
            float w = c.y * invl;
            const float* vr = g_v + (size_t)j * D_V + d;
            float4 v0 = *(const float4*)(vr);
            float4 v1 = *(const float4*)(vr + 4);
            float4 v2 = *(const float4*)(vr + 8);
            float4 v3 = *(const float4*)(vr + 12);
            a0.x += w * v0.x; a0.y += w * v0.y; a0.z += w * v0.z; a0.w += w * v0.w;
            a1.x += w * v1.x; a1.y += w * v1.y; a1.z += w * v1.z; a1.w += w * v1.w;
            a2.x += w * v2.x; a2.y += w * v2.y; a2.z += w * v2.z; a2.w += w * v2.w;
            a3.x += w * v3.x; a3.y += w * v3.y; a3.z += w * v3.z; a3.w += w * v3.w;
        }
    } else {
        const float m = g_m[r];
        const float* Srow = g_S + (size_t)r * N_TOK;
        for (int j = 0; j < N_TOK; j++) {
            float w = __expf(Srow[j] - m) * invl;
            if (w > 1e-12f) {
                const float* vr = g_v + (size_t)j * D_V + d;
                float4 v0 = *(const float4*)(vr);
                float4 v1 = *(const float4*)(vr + 4);
                float4 v2 = *(const float4*)(vr + 8);
                float4 v3 = *(const float4*)(vr + 12);
                a0.x += w * v0.x; a0.y += w * v0.y; a0.z += w * v0.z; a0.w += w * v0.w;
                a1.x += w * v1.x; a1.y += w * v1.y; a1.z += w * v1.z; a1.w += w * v1.w;
                a2.x += w * v2.x; a2.y += w * v2.y; a2.z += w * v2.z; a2.w += w * v2.w;
                a3.x += w * v3.x; a3.y += w * v3.y; a3.z += w * v3.z; a3.w += w * v3.w;
            }
        }
    }

    float* out = g_sa + (size_t)r * D_V + d;
    *(float4*)(out)      = a0;
    *(float4*)(out + 4)  = a1;
    *(float4*)(out + 8)  = a2;
    *(float4*)(out + 12) = a3;
}

// ---------------- fused residual + LayerNorm ----------------
__global__ __launch_bounds__(256)
void ln_fuse(int mode, const float* __restrict__ ext_a, float* __restrict__ ext_out)
{
    const int r   = blockIdx.x;
    const int tid = threadIdx.x;
    const float* a; const float* b;
    if (mode == 0) { a = ext_a; b = g_sa; }
    else           { a = g_sa;  b = g_tmp; }

    const float4 av = *(const float4*)(a + (size_t)r * D_V + tid * 4);
    const float4 bv = *(const float4*)(b + (size_t)r * D_V + tid * 4);
    float4 y = make_float4(av.x + bv.x, av.y + bv.y, av.z + bv.z, av.w + bv.w);

    float s  = y.x + y.y + y.z + y.w;
    float sq = y.x * y.x + y.y * y.y + y.z * y.z + y.w * y.w;

    __shared__ float2 red2[256];
    red2[tid] = make_float2(s, sq);
    __syncthreads();
    for (int st = 128; st > 0; st >>= 1) {
        if (tid < st) {
            red2[tid].x += red2[tid + st].x;
            red2[tid].y += red2[tid + st].y;
        }
        __syncthreads();
    }
    const float mean = red2[0].x * (1.0f / (float)D_V);
    const float var  = red2[0].y * (1.0f / (float)D_V) - mean * mean;
    const float rstd = rsqrtf(var + 1e-5f);

    float o0 = (y.x - mean) * rstd, o1 = (y.y - mean) * rstd;
    float o2 = (y.z - mean) * rstd, o3 = (y.w - mean) * rstd;

    if (mode == 0) {
        size_t base = (size_t)r * D_V + tid * 4;
        split_bf16(o0, g_hh[base + 0], g_hl[base + 0]);
        split_bf16(o1, g_hh[base + 1], g_hl[base + 1]);
        split_bf16(o2, g_hh[base + 2], g_hl[base + 2]);
        split_bf16(o3, g_hh[base + 3], g_hl[base + 3]);
    } else {
        *(float4*)(ext_out + (size_t)r * D_V + tid * 4) = make_float4(o0, o1, o2, o3);
    }
}

// ---------------- launch sequence ----------------
extern "C" void kernel_launch(void* const* d_in, const int* in_sizes, int n_in,
                              void* d_out, int out_size)
{
    const float* x  = (const float*)d_in[0];
    const float* Wq = (const float*)d_in[1];
    const float* Wk = (const float*)d_in[2];
    const float* Wv = (const float*)d_in[3];
    const float* Wl = (const float*)d_in[4];
    float* out = (float*)d_out;

    cudaFuncSetAttribute(gemm_mma, cudaFuncAttributeMaxDynamicSharedMemorySize, SMEM_BYTES);

    prep_weights<<<256, 256>>>(Wq, Wk, Wv, Wl);
    split_x<<<512, 256>>>(x);

    // qkv = x @ W1^T  (M=8192, N=1280, K=1024) -> qk bf16 split + v fp32
    gemm_mma<<<NSM, 256, SMEM_BYTES>>>(0);

    // S = sqrt(128) * q @ k^T  (M=N=8192, K=128) + row-max atomics
    gemm_mma<<<NSM, 256, SMEM_BYTES>>>(1);

    softmax_stats<<<N_TOK, 256>>>();
    attn_av<<<N_TOK, 64>>>();
    ln_fuse<<<N_TOK, 256>>>(0, x, nullptr);

    // tmp = h @ Wl^T  (M=8192, N=1024, K=1024)
    gemm_mma<<<NSM, 256, SMEM_BYTES>>>(2);

    ln_fuse<<<N_TOK, 256>>>(1, nullptr, out);
}

// round 9
// speedup vs baseline: 1.0288x; 1.0143x over previous
#include <cuda_runtime.h>
#include <cuda_bf16.h>
#include <cstdint>
#include <math.h>

// Problem dims (fixed by the dataset)
#define N_TOK 8192
#define D_IN  1024
#define D_QK  128
#define D_V   1024
#define D_W1  1280   // concat rows: Wq(128) | Wk(128) | Wv(1024)
#define CAP   1024
#define NSM   148
#define ALPHA 11.313708498984760f   // sqrt(128)

// ---------------- scratch (static device globals; no allocs) ----------------
static __device__ __align__(16) __nv_bfloat16 g_xh [(size_t)N_TOK * D_IN];
static __device__ __align__(16) __nv_bfloat16 g_xl [(size_t)N_TOK * D_IN];
static __device__ __align__(16) __nv_bfloat16 g_W1h[(size_t)D_W1 * D_IN];
static __device__ __align__(16) __nv_bfloat16 g_W1l[(size_t)D_W1 * D_IN];
static __device__ __align__(16) __nv_bfloat16 g_Wlh[(size_t)D_V * D_IN];
static __device__ __align__(16) __nv_bfloat16 g_Wll[(size_t)D_V * D_IN];
static __device__ __align__(16) __nv_bfloat16 g_qkh[(size_t)N_TOK * 256];  // bf16 q|k (hi)
static __device__ __align__(16) float         g_qk [(size_t)N_TOK * 256];  // fp32 q|k (exact)
static __device__ __align__(16) __nv_bfloat16 g_hh [(size_t)N_TOK * D_IN];
static __device__ __align__(16) __nv_bfloat16 g_hl [(size_t)N_TOK * D_IN];
static __device__ float  g_v  [(size_t)N_TOK * D_V];
static __device__ __align__(16) __nv_bfloat16 g_Sb[(size_t)N_TOK * N_TOK]; // 128 MB approx scores
static __device__ float  g_m  [N_TOK];
static __device__ int    g_cnt[N_TOK];
static __device__ float2 g_cand[(size_t)N_TOK * CAP];
static __device__ float  g_sa [(size_t)N_TOK * D_V];
static __device__ float  g_tmp[(size_t)N_TOK * D_V];

// ---------------- helpers ----------------
__device__ __forceinline__ uint32_t smem_u32(const void* p) {
    uint32_t a;
    asm("{ .reg .u64 t; cvta.to.shared.u64 t, %1; cvt.u32.u64 %0, t; }" : "=r"(a) : "l"(p));
    return a;
}
__device__ __forceinline__ void split_bf16(float v, __nv_bfloat16& h, __nv_bfloat16& l) {
    h = __float2bfloat16(v);
    l = __float2bfloat16(v - __bfloat162float(h));
}
__device__ __forceinline__ void atomicMaxFloat(float* addr, float v) {
    if (v >= 0.0f) atomicMax((int*)addr, __float_as_int(v));
    else           atomicMin((unsigned int*)addr, __float_as_uint(v));
}

#define LDSM_X4(r, addr)                                                        \
    asm volatile("ldmatrix.sync.aligned.m8n8.x4.shared.b16 {%0,%1,%2,%3}, [%4];" \
        : "=r"((r)[0]), "=r"((r)[1]), "=r"((r)[2]), "=r"((r)[3]) : "r"(addr))

#define MMA_BF16(c, a, b)                                                       \
    asm volatile("mma.sync.aligned.m16n8k16.row.col.f32.bf16.bf16.f32 "         \
        "{%0,%1,%2,%3}, {%4,%5,%6,%7}, {%8,%9}, {%0,%1,%2,%3};"                 \
        : "+f"((c)[0]), "+f"((c)[1]), "+f"((c)[2]), "+f"((c)[3])                \
        : "r"((a)[0]), "r"((a)[1]), "r"((a)[2]), "r"((a)[3]),                   \
          "r"((b)[0]), "r"((b)[1]))

#define CP_ASYNC16(dst, src) \
    asm volatile("cp.async.cg.shared.global [%0], [%1], 16;" :: "r"(dst), "l"(src))
#define CP_COMMIT()  asm volatile("cp.async.commit_group;")
#define CP_WAIT(n)   asm volatile("cp.async.wait_group %0;" :: "n"(n))

// ---------------- weight / input prep: bf16 hi-lo split ----------------
__global__ void prep_weights(const float* __restrict__ Wq, const float* __restrict__ Wk,
                             const float* __restrict__ Wv, const float* __restrict__ Wl)
{
    const int stride = gridDim.x * blockDim.x;
    int g = blockIdx.x * blockDim.x + threadIdx.x;
    for (int i = g; i < D_W1 * D_IN; i += stride) {
        int r = i >> 10, c = i & 1023;
        float v;
        if (r < 128)      v = Wq[r * D_IN + c];
        else if (r < 256) v = Wk[(r - 128) * D_IN + c];
        else              v = Wv[(r - 256) * D_IN + c];
        split_bf16(v, g_W1h[i], g_W1l[i]);
    }
    for (int i = g; i < D_V * D_IN; i += stride)
        split_bf16(Wl[i], g_Wlh[i], g_Wll[i]);
}

__global__ void split_x(const float* __restrict__ x)
{
    const int stride = gridDim.x * blockDim.x;
    int g = blockIdx.x * blockDim.x + threadIdx.x;
    for (int i = g; i < N_TOK * D_IN; i += stride)
        split_bf16(x[i], g_xh[i], g_xl[i]);
    for (int i = g; i < N_TOK; i += stride)
        g_m[i] = -1e30f;
}

// ---------------- bf16 tensor-core GEMM (PERSISTENT, templated) -------------
// MODE 0: qkv = x @ W1^T   (bf16x3, K=1024)  -> q,k fp32+bf16 ; v fp32
// MODE 1: S~  = alpha*q@k^T (bf16x1, K=128)  -> g_Sb bf16 + row-max atomics
// MODE 2: tmp = h @ Wl^T   (bf16x3, K=1024)  -> g_tmp fp32
#define TILE_B   16384          // one 128x64 bf16 tile (swizzled)

template<int MODE>
__global__ __launch_bounds__(256, 1)
void gemm_mma()
{
    constexpr int NT    = (MODE == 1) ? 2 : 4;   // tiles per stage
    constexpr int STAGE = NT * TILE_B;
    extern __shared__ char smem[];
    const uint32_t sb  = smem_u32(smem);
    const int tid  = threadIdx.x;
    const int wid  = tid >> 5;
    const int lane = tid & 31;

    const __nv_bfloat16 *Ah, *Al = nullptr, *Bh, *Bl = nullptr;
    constexpr int lda = (MODE == 1) ? 256 : 1024;
    constexpr int ldb = (MODE == 1) ? 256 : 1024;
    constexpr int K   = (MODE == 1) ? 128 : 1024;
    constexpr int ntn = (MODE == 0) ? 10 : (MODE == 1 ? 64 : 8);
    if constexpr (MODE == 0)      { Ah = g_xh;  Al = g_xl; Bh = g_W1h;       Bl = g_W1l; }
    else if constexpr (MODE == 1) { Ah = g_qkh;            Bh = g_qkh + 128; }
    else                          { Ah = g_hh;  Al = g_hl; Bh = g_Wlh;       Bl = g_Wll; }

    constexpr int nch  = K / 64;
    constexpr int ntot = ntn * (N_TOK / 128);

    auto load_stage = [&](int st, int t, int k0) {
        const int tm0 = (t / ntn) * 128;
        const int tn0 = (t % ntn) * 128;
        const __nv_bfloat16* bs[NT];
        if constexpr (MODE == 1) {
            bs[0] = Ah + (size_t)tm0 * lda;
            bs[1] = Bh + (size_t)tn0 * ldb;
        } else {
            bs[0] = Ah + (size_t)tm0 * lda;
            bs[1] = Al + (size_t)tm0 * lda;
            bs[2] = Bh + (size_t)tn0 * ldb;
            bs[3] = Bl + (size_t)tn0 * ldb;
        }
#pragma unroll
        for (int it = 0; it < NT * 4; it++) {
            int idx  = tid + it * 256;
            int tile = idx >> 10;
            int r    = (idx >> 3) & 127;
            int g    = idx & 7;
            const __nv_bfloat16* src = bs[tile] + (size_t)r * lda + k0 + g * 8;
            uint32_t off = (uint32_t)(r * 128 + g * 16);
            off ^= (off >> 3) & 0x70;
            CP_ASYNC16(sb + st * STAGE + tile * TILE_B + off, src);
        }
        CP_COMMIT();
    };

    const int wm = (wid & 3) * 32;
    const int wn = (wid >> 2) * 64;

    float acc[2][8][4];

    constexpr int AH_T = 0;
    constexpr int AL_T = 1;
    constexpr int BH_T = (MODE == 1) ? 1 : 2;
    constexpr int BL_T = 3;

    auto load_frags = [&](uint32_t base, int k16,
                          uint32_t (*ah)[4], uint32_t (*al)[4],
                          uint32_t (*bh)[4], uint32_t (*bl)[4]) {
#pragma unroll
        for (int mi = 0; mi < 2; mi++) {
            int row = wm + mi * 16 + (lane & 15);
            int c16 = k16 * 2 + (lane >> 4);
            uint32_t off = (uint32_t)(row * 128 + c16 * 16);
            off ^= (off >> 3) & 0x70;
            LDSM_X4(ah[mi], base + AH_T * TILE_B + off);
            if constexpr (MODE != 1) LDSM_X4(al[mi], base + AL_T * TILE_B + off);
        }
#pragma unroll
        for (int nj = 0; nj < 4; nj++) {
            int row = wn + nj * 16 + (lane & 7) + ((lane >> 4) << 3);
            int c16 = k16 * 2 + ((lane >> 3) & 1);
            uint32_t off = (uint32_t)(row * 128 + c16 * 16);
            off ^= (off >> 3) & 0x70;
            LDSM_X4(bh[nj], base + BH_T * TILE_B + off);
            if constexpr (MODE != 1) LDSM_X4(bl[nj], base + BL_T * TILE_B + off);
        }
    };

    auto compute_stage = [&](int st) {
        const uint32_t base = sb + st * STAGE;
        uint32_t ah[2][2][4], al[2][2][4], bh[2][4][4], bl[2][4][4];
        load_frags(base, 0, ah[0], al[0], bh[0], bl[0]);
#pragma unroll
        for (int k16 = 0; k16 < 4; k16++) {
            const int cur = k16 & 1;
#pragma unroll
            for (int mi = 0; mi < 2; mi++)
#pragma unroll
                for (int nj = 0; nj < 4; nj++) {
                    MMA_BF16(acc[mi][nj * 2],     ah[cur][mi], (bh[cur][nj] + 0));
                    MMA_BF16(acc[mi][nj * 2 + 1], ah[cur][mi], (bh[cur][nj] + 2));
                }
            if (k16 < 3)
                load_frags(base, k16 + 1, ah[cur ^ 1], al[cur ^ 1],
                           bh[cur ^ 1], bl[cur ^ 1]);
            if constexpr (MODE != 1) {
#pragma unroll
                for (int mi = 0; mi < 2; mi++)
#pragma unroll
                    for (int nj = 0; nj < 4; nj++) {
                        MMA_BF16(acc[mi][nj * 2],     ah[cur][mi], (bl[cur][nj] + 0));
                        MMA_BF16(acc[mi][nj * 2 + 1], ah[cur][mi], (bl[cur][nj] + 2));
                    }
#pragma unroll
                for (int mi = 0; mi < 2; mi++)
#pragma unroll
                    for (int nj = 0; nj < 4; nj++) {
                        MMA_BF16(acc[mi][nj * 2],     al[cur][mi], (bh[cur][nj] + 0));
                        MMA_BF16(acc[mi][nj * 2 + 1], al[cur][mi], (bh[cur][nj] + 2));
                    }
            }
        }
    };

    const int qr = lane >> 2;
    const int qc = (lane & 3) * 2;

    auto epilogue = [&](int t) {
        const int m0 = (t / ntn) * 128;
        const int n0 = (t % ntn) * 128;
        if constexpr (MODE == 1) {
            float rmax0[2] = { -1e30f, -1e30f };
            float rmax1[2] = { -1e30f, -1e30f };
#pragma unroll
            for (int mi = 0; mi < 2; mi++) {
                const int r0 = m0 + wm + mi * 16 + qr;
#pragma unroll
                for (int ni = 0; ni < 8; ni++) {
                    const int col = n0 + wn + ni * 8 + qc;
                    float c0 = ALPHA * acc[mi][ni][0], c1 = ALPHA * acc[mi][ni][1];
                    float c2 = ALPHA * acc[mi][ni][2], c3 = ALPHA * acc[mi][ni][3];
                    rmax0[mi] = fmaxf(rmax0[mi], fmaxf(c0, c1));
                    rmax1[mi] = fmaxf(rmax1[mi], fmaxf(c2, c3));
                    *(__nv_bfloat162*)(g_Sb + (size_t)r0 * N_TOK + col) =
                        __nv_bfloat162(__float2bfloat16(c0), __float2bfloat16(c1));
                    *(__nv_bfloat162*)(g_Sb + (size_t)(r0 + 8) * N_TOK + col) =
                        __nv_bfloat162(__float2bfloat16(c2), __float2bfloat16(c3));
                }
            }
#pragma unroll
            for (int mi = 0; mi < 2; mi++) {
#pragma unroll
                for (int s = 1; s < 4; s <<= 1) {
                    rmax0[mi] = fmaxf(rmax0[mi], __shfl_xor_sync(0xFFFFFFFF, rmax0[mi], s));
                    rmax1[mi] = fmaxf(rmax1[mi], __shfl_xor_sync(0xFFFFFFFF, rmax1[mi], s));
                }
                if ((lane & 3) == 0) {
                    const int r0 = m0 + wm + mi * 16 + qr;
                    atomicMaxFloat(&g_m[r0],     rmax0[mi]);
                    atomicMaxFloat(&g_m[r0 + 8], rmax1[mi]);
                }
            }
        } else if constexpr (MODE == 0) {
#pragma unroll
            for (int mi = 0; mi < 2; mi++) {
                const int r0 = m0 + wm + mi * 16 + qr;
#pragma unroll
                for (int ni = 0; ni < 8; ni++) {
                    const int col = n0 + wn + ni * 8 + qc;
                    if (col < 256) {
#pragma unroll
                        for (int half = 0; half < 2; half++) {
                            const int rr = r0 + half * 8;
                            float v0 = acc[mi][ni][half * 2 + 0];
                            float v1 = acc[mi][ni][half * 2 + 1];
                            *(float2*)(g_qk + (size_t)rr * 256 + col) = make_float2(v0, v1);
                            *(__nv_bfloat162*)(g_qkh + (size_t)rr * 256 + col) =
                                __nv_bfloat162(__float2bfloat16(v0), __float2bfloat16(v1));
                        }
                    } else {
                        const int vc = col - 256;
                        *(float2*)(g_v + (size_t)r0 * D_V + vc) =
                            make_float2(acc[mi][ni][0], acc[mi][ni][1]);
                        *(float2*)(g_v + (size_t)(r0 + 8) * D_V + vc) =
                            make_float2(acc[mi][ni][2], acc[mi][ni][3]);
                    }
                }
            }
        } else {
#pragma unroll
            for (int mi = 0; mi < 2; mi++) {
                const int r0 = m0 + wm + mi * 16 + qr;
#pragma unroll
                for (int ni = 0; ni < 8; ni++) {
                    const int col = n0 + wn + ni * 8 + qc;
                    *(float2*)(g_tmp + (size_t)r0 * D_V + col) =
                        make_float2(acc[mi][ni][0], acc[mi][ni][1]);
                    *(float2*)(g_tmp + (size_t)(r0 + 8) * D_V + col) =
                        make_float2(acc[mi][ni][2], acc[mi][ni][3]);
                }
            }
        }
    };

    int t0 = blockIdx.x;
    if (t0 >= ntot) return;
    load_stage(0, t0, 0);
    int buf = 0;

    for (int t = t0; t < ntot; t += gridDim.x) {
        const int tnext = t + gridDim.x;
#pragma unroll
        for (int i = 0; i < 2; i++)
#pragma unroll
            for (int j = 0; j < 8; j++)
#pragma unroll
                for (int k = 0; k < 4; k++) acc[i][j][k] = 0.0f;

        for (int ch = 0; ch < nch; ch++) {
            const bool more_chunk = (ch + 1 < nch);
            if (more_chunk)            load_stage(buf ^ 1, t, (ch + 1) * 64);
            else if (tnext < ntot)     load_stage(buf ^ 1, tnext, 0);
            if (more_chunk || tnext < ntot) { CP_WAIT(1); }
            else                            { CP_WAIT(0); }
            __syncthreads();
            compute_stage(buf);
            buf ^= 1;
            __syncthreads();
        }
        epilogue(t);
    }
}

// ---------------- candidate scan over approximate bf16 scores ---------------
// Keeps every j whose EXACT logit could be >= m - 25: threshold uses worst-case
// single-term GEMM error (~2.5) + bf16 storage rounding, with generous slack.
__global__ __launch_bounds__(256)
void candidate_scan()
{
    const int r   = blockIdx.x;
    const int tid = threadIdx.x;
    const float mt  = g_m[r];
    const float thr = mt - (50.0f + (fabsf(mt) + 100.0f) * 0.001953125f);

    __shared__ int sc[256];
    __shared__ int s_over;
    if (tid == 0) s_over = 0;
    __syncthreads();

    const uint4* row = (const uint4*)(g_Sb + (size_t)r * N_TOK);
    int lj[8]; int lc = 0, over = 0;
#pragma unroll
    for (int it = 0; it < 4; it++) {
        int v4 = tid + it * 256;        // each uint4 = 8 bf16
        uint4 u = row[v4];
        const __nv_bfloat16* p = (const __nv_bfloat16*)&u;
        int jb = v4 * 8;
#pragma unroll
        for (int e = 0; e < 8; e++) {
            float s = __bfloat162float(p[e]);
            if (s > thr) {
                if (lc < 8) lj[lc] = jb + e;
                else over = 1;
                lc++;
            }
        }
    }
    if (over) atomicOr(&s_over, 1);

    sc[tid] = lc;
    __syncthreads();
    for (int off = 1; off < 256; off <<= 1) {
        int tsc = (tid >= off) ? sc[tid - off] : 0;
        __syncthreads();
        sc[tid] += tsc;
        __syncthreads();
    }
    const int total = sc[255];
    const int myoff = sc[tid] - lc;
    const int dense = (total > CAP) || (s_over != 0);

    if (!dense) {
        const int n = (lc < 8) ? lc : 8;
        for (int i = 0; i < n; i++)
            g_cand[(size_t)r * CAP + myoff + i] =
                make_float2(__int_as_float(lj[i]), 0.0f);
    }
    if (tid == 0) g_cnt[r] = dense ? (CAP + 1) : total;
}

// ---------------- exact softmax over candidates (fp32 q,k) ------------------
__global__ __launch_bounds__(128)
void exact_softmax()
{
    const int r    = blockIdx.x;
    const int tid  = threadIdx.x;
    const int wrp  = tid >> 5;
    const int lane = tid & 31;
    const int cnt  = g_cnt[r];
    if (cnt > CAP) return;  // dense fallback handled in attn_av

    __shared__ float ss[CAP];
    __shared__ float smax, ssum;

    const float4* qv = (const float4*)(g_qk + (size_t)r * 256);
    float4 q = qv[lane >> 3 & 3];  // placeholder; real load below per candidate
    (void)q;

    for (int c = wrp; c < cnt; c += 4) {
        int j = __float_as_int(g_cand[(size_t)r * CAP + c].x);
        const float4 qf = *(const float4*)(g_qk + (size_t)r * 256 + lane * 4);
        const float4 kf = *(const float4*)(g_qk + (size_t)j * 256 + 128 + lane * 4);
        float p = qf.x * kf.x + qf.y * kf.y + qf.z * kf.z + qf.w * kf.w;
#pragma unroll
        for (int s = 16; s; s >>= 1) p += __shfl_xor_sync(0xFFFFFFFF, p, s);
        if (lane == 0) ss[c] = ALPHA * p;
    }
    __syncthreads();

    if (tid == 0) {
        float mx = -1e30f;
        for (int c = 0; c < cnt; c++) mx = fmaxf(mx, ss[c]);
        float l = 0.0f;
        for (int c = 0; c < cnt; c++) l += __expf(ss[c] - mx);
        smax = mx; ssum = l;
    }
    __syncthreads();

    const float mx = smax, invl = 1.0f / ssum;
    for (int c = tid; c < cnt; c += 128)
        g_cand[(size_t)r * CAP + c].y = __expf(ss[c] - mx) * invl;
}

// ---------------- sparse attn@v (weights pre-normalized) --------------------
__global__ __launch_bounds__(64)
void attn_av()
{
    const int r   = blockIdx.x;
    const int tid = threadIdx.x;
    const int cnt = g_cnt[r];
    const int d   = tid * 16;

    float4 a0 = make_float4(0, 0, 0, 0), a1 = a0, a2 = a0, a3 = a0;

    if (cnt <= CAP) {
        const float2* cl = g_cand + (size_t)r * CAP;
        for (int i = 0; i < cnt; i++) {
            float2 c = cl[i];
            int   j = __float_as_int(c.x);
            float w = c.y;
            const float* vr = g_v + (size_t)j * D_V + d;
            float4 v0 = *(const float4*)(vr);
            float4 v1 = *(const float4*)(vr + 4);
            float4 v2 = *(const float4*)(vr + 8);
            float4 v3 = *(const float4*)(vr + 12);
            a0.x += w * v0.x; a0.y += w * v0.y; a0.z += w * v0.z; a0.w += w * v0.w;
            a1.x += w * v1.x; a1.y += w * v1.y; a1.z += w * v1.z; a1.w += w * v1.w;
            a2.x += w * v2.x; a2.y += w * v2.y; a2.z += w * v2.z; a2.w += w * v2.w;
            a3.x += w * v3.x; a3.y += w * v3.y; a3.z += w * v3.z; a3.w += w * v3.w;
        }
    } else {
        // exact dense recompute from fp32 q,k (adversarial-only path)
        __shared__ float sw[64];
        __shared__ float sred[64];
        const float* qf = g_qk + (size_t)r * 256;
        float mx = -1e30f;
        for (int jb = 0; jb < N_TOK; jb += 64) {
            const float* kf = g_qk + (size_t)(jb + tid) * 256 + 128;
            float s = 0.0f;
            for (int e = 0; e < 128; e++) s += qf[e] * kf[e];
            mx = fmaxf(mx, ALPHA * s);
        }
        sred[tid] = mx;
        __syncthreads();
        for (int st = 32; st; st >>= 1) {
            if (tid < st) sred[tid] = fmaxf(sred[tid], sred[tid + st]);
            __syncthreads();
        }
        mx = sred[0];
        float l = 0.0f;
        for (int jb = 0; jb < N_TOK; jb += 64) {
            const float* kf = g_qk + (size_t)(jb + tid) * 256 + 128;
            float s = 0.0f;
            for (int e = 0; e < 128; e++) s += qf[e] * kf[e];
            sw[tid] = __expf(ALPHA * s - mx);
            __syncthreads();
            for (int jj = 0; jj < 64; jj++) {
                float w = sw[jj];
                l += w;
                const float* vr = g_v + (size_t)(jb + jj) * D_V + d;
                float4 v0 = *(const float4*)(vr);
                float4 v1 = *(const float4*)(vr + 4);
                float4 v2 = *(const float4*)(vr + 8);
                float4 v3 = *(const float4*)(vr + 12);
                a0.x += w * v0.x; a0.y += w * v0.y; a0.z += w * v0.z; a0.w += w * v0.w;
                a1.x += w * v1.x; a1.y += w * v1.y; a1.z += w * v1.z; a1.w += w * v1.w;
                a2.x += w * v2.x; a2.y += w * v2.y; a2.z += w * v2.z; a2.w += w * v2.w;
                a3.x += w * v3.x; a3.y += w * v3.y; a3.z += w * v3.z; a3.w += w * v3.w;
            }
            __syncthreads();
        }
        const float inv = 1.0f / l;
        a0.x *= inv; a0.y *= inv; a0.z *= inv; a0.w *= inv;
        a1.x *= inv; a1.y *= inv; a1.z *= inv; a1.w *= inv;
        a2.x *= inv; a2.y *= inv; a2.z *= inv; a2.w *= inv;
        a3.x *= inv; a3.y *= inv; a3.z *= inv; a3.w *= inv;
    }

    float* out = g_sa + (size_t)r * D_V + d;
    *(float4*)(out)      = a0;
    *(float4*)(out + 4)  = a1;
    *(float4*)(out + 8)  = a2;
    *(float4*)(out + 12) = a3;
}

// ---------------- fused residual + LayerNorm ----------------
__global__ __launch_bounds__(256)
void ln_fuse(int mode, const float* __restrict__ ext_a, float* __restrict__ ext_out)
{
    const int r   = blockIdx.x;
    const int tid = threadIdx.x;
    const float* a; const float* b;
    if (mode == 0) { a = ext_a; b = g_sa; }
    else           { a = g_sa;  b = g_tmp; }

    const float4 av = *(const float4*)(a + (size_t)r * D_V + tid * 4);
    const float4 bv = *(const float4*)(b + (size_t)r * D_V + tid * 4);
    float4 y = make_float4(av.x + bv.x, av.y + bv.y, av.z + bv.z, av.w + bv.w);

    float s  = y.x + y.y + y.z + y.w;
    float sq = y.x * y.x + y.y * y.y + y.z * y.z + y.w * y.w;

    __shared__ float2 red2[256];
    red2[tid] = make_float2(s, sq);
    __syncthreads();
    for (int st = 128; st > 0; st >>= 1) {
        if (tid < st) {
            red2[tid].x += red2[tid + st].x;
            red2[tid].y += red2[tid + st].y;
        }
        __syncthreads();
    }
    const float mean = red2[0].x * (1.0f / (float)D_V);
    const float var  = red2[0].y * (1.0f / (float)D_V) - mean * mean;
    const float rstd = rsqrtf(var + 1e-5f);

    float o0 = (y.x - mean) * rstd, o1 = (y.y - mean) * rstd;
    float o2 = (y.z - mean) * rstd, o3 = (y.w - mean) * rstd;

    if (mode == 0) {
        size_t base = (size_t)r * D_V + tid * 4;
        split_bf16(o0, g_hh[base + 0], g_hl[base + 0]);
        split_bf16(o1, g_hh[base + 1], g_hl[base + 1]);
        split_bf16(o2, g_hh[base + 2], g_hl[base + 2]);
        split_bf16(o3, g_hh[base + 3], g_hl[base + 3]);
    } else {
        *(float4*)(ext_out + (size_t)r * D_V + tid * 4) = make_float4(o0, o1, o2, o3);
    }
}

// ---------------- launch sequence ----------------
extern "C" void kernel_launch(void* const* d_in, const int* in_sizes, int n_in,
                              void* d_out, int out_size)
{
    const float* x  = (const float*)d_in[0];
    const float* Wq = (const float*)d_in[1];
    const float* Wk = (const float*)d_in[2];
    const float* Wv = (const float*)d_in[3];
    const float* Wl = (const float*)d_in[4];
    float* out = (float*)d_out;

    cudaFuncSetAttribute(gemm_mma<0>, cudaFuncAttributeMaxDynamicSharedMemorySize, 8 * TILE_B);
    cudaFuncSetAttribute(gemm_mma<1>, cudaFuncAttributeMaxDynamicSharedMemorySize, 4 * TILE_B);
    cudaFuncSetAttribute(gemm_mma<2>, cudaFuncAttributeMaxDynamicSharedMemorySize, 8 * TILE_B);

    prep_weights<<<256, 256>>>(Wq, Wk, Wv, Wl);
    split_x<<<512, 256>>>(x);

    gemm_mma<0><<<NSM, 256, 8 * TILE_B>>>();   // qkv projection (bf16x3)
    gemm_mma<1><<<NSM, 256, 4 * TILE_B>>>();   // approx scores (bf16x1) + row max

    candidate_scan<<<N_TOK, 256>>>();
    exact_softmax<<<N_TOK, 128>>>();
    attn_av<<<N_TOK, 64>>>();
    ln_fuse<<<N_TOK, 256>>>(0, x, nullptr);

    gemm_mma<2><<<NSM, 256, 8 * TILE_B>>>();   // output projection (bf16x3)

    ln_fuse<<<N_TOK, 256>>>(1, nullptr, out);
}